// round 15
// baseline (speedup 1.0000x reference)
#include <cuda_runtime.h>
#include <cuda_bf16.h>
#include <math.h>
#include <stdint.h>
#include <stddef.h>

// ---------------- problem constants ----------------
#define T_STEPS 2048
#define BATCH   64
#define D_IN    512
#define D_HID   512
#define MROWS   (T_STEPS * BATCH)        // 131072
#define XCOLS   1536                     // r | z | g pre-activations from x

// ---------------- recurrent kernel topology ----------------
#define NGROUPS 8
#define CPG     16                       // CTAs per group == cluster size
#define NCTAS   (NGROUPS * CPG)          // 128
#define BLOC    (BATCH / NGROUPS)        // 8
#define RPC     (D_HID / CPG)            // 32
#define RTHREADS 512

// ---------------- device scratch (static; no allocation APIs) ----------------
__device__ float g_Xbuf[(size_t)MROWS * XCOLS];

// bf16 hi/lo split operands for the tensor-core xproj
__device__ __nv_bfloat16 g_xhi[(size_t)MROWS * D_IN];   // 128 MB
__device__ __nv_bfloat16 g_xlo[(size_t)MROWS * D_IN];   // 128 MB
__device__ __nv_bfloat16 g_whi[XCOLS * D_IN];           // 1.5 MB
__device__ __nv_bfloat16 g_wlo[XCOLS * D_IN];

// ---------------- mma.sync / ldmatrix / cp.async helpers (sm_80+ PTX) ------
__device__ __forceinline__ uint32_t smem_u32(const void* p) {
    uint32_t a;
    asm("{ .reg .u64 t; cvta.to.shared.u64 t, %1; cvt.u32.u64 %0, t; }"
        : "=r"(a) : "l"(p));
    return a;
}
__device__ __forceinline__ void ldm4(uint32_t* r, uint32_t addr) {
    asm volatile("ldmatrix.sync.aligned.m8n8.x4.shared.b16 {%0,%1,%2,%3}, [%4];"
                 : "=r"(r[0]), "=r"(r[1]), "=r"(r[2]), "=r"(r[3]) : "r"(addr));
}
__device__ __forceinline__ void mma16816(float* c, const uint32_t* a,
                                         const uint32_t* b) {
    asm volatile(
        "mma.sync.aligned.m16n8k16.row.col.f32.bf16.bf16.f32 "
        "{%0,%1,%2,%3}, {%4,%5,%6,%7}, {%8,%9}, {%0,%1,%2,%3};"
        : "+f"(c[0]), "+f"(c[1]), "+f"(c[2]), "+f"(c[3])
        : "r"(a[0]), "r"(a[1]), "r"(a[2]), "r"(a[3]), "r"(b[0]), "r"(b[1]));
}
__device__ __forceinline__ void cp16(uint32_t dst, const void* src) {
    asm volatile("cp.async.cg.shared.global [%0], [%1], 16;"
                 :: "r"(dst), "l"(__cvta_generic_to_global(src)) : "memory");
}
#define CP_COMMIT() asm volatile("cp.async.commit_group;" ::: "memory")
#define CP_WAIT1()  asm volatile("cp.async.wait_group 1;" ::: "memory")
#define CP_WAIT0()  asm volatile("cp.async.wait_group 0;" ::: "memory")

// ---------------- cluster / DSMEM primitives (sm_90+ baseline PTX) ---------
#define CLUSTER_ARRIVE() asm volatile("barrier.cluster.arrive.aligned;" ::: "memory")
#define CLUSTER_WAIT()   asm volatile("barrier.cluster.wait.aligned;" ::: "memory")

__device__ __forceinline__ uint32_t mapa_u32(uint32_t local, uint32_t rank) {
    uint32_t rem;
    asm("mapa.shared::cluster.u32 %0, %1, %2;" : "=r"(rem) : "r"(local), "r"(rank));
    return rem;
}
__device__ __forceinline__ void st_cluster_v4(uint32_t rem, float4 v) {
    asm volatile("st.shared::cluster.v4.f32 [%0], {%1,%2,%3,%4};"
                 :: "r"(rem), "f"(v.x), "f"(v.y), "f"(v.z), "f"(v.w) : "memory");
}

// =====================================================================
// split kernels: fp32 -> bf16 hi + bf16 lo   (unchanged from R14)
// =====================================================================
__global__ void __launch_bounds__(256) split_x_kernel(const float* __restrict__ x) {
    size_t i4 = (size_t)blockIdx.x * 256 + threadIdx.x;
    float4 v = ((const float4*)x)[i4];
    float vv[4] = {v.x, v.y, v.z, v.w};
    __nv_bfloat16 hi[4], lo[4];
#pragma unroll
    for (int j = 0; j < 4; j++) {
        hi[j] = __float2bfloat16(vv[j]);
        lo[j] = __float2bfloat16(vv[j] - __bfloat162float(hi[j]));
    }
    ((uint2*)g_xhi)[i4] = *(uint2*)hi;
    ((uint2*)g_xlo)[i4] = *(uint2*)lo;
}

__global__ void __launch_bounds__(256) split_w_kernel(
    const float* __restrict__ Wr, const float* __restrict__ Wz,
    const float* __restrict__ Wg)
{
    size_t i4 = (size_t)blockIdx.x * 256 + threadIdx.x;
    size_t e = i4 * 4;
    int n = (int)(e >> 9);
    int k = (int)(e & 511);
    int gate = n >> 9;
    int nr = n & 511;
    const float* W = (gate == 0) ? Wr : (gate == 1) ? Wz : Wg;
    float4 v = *(const float4*)&W[(size_t)nr * 1024 + k];
    float vv[4] = {v.x, v.y, v.z, v.w};
    __nv_bfloat16 hi[4], lo[4];
#pragma unroll
    for (int j = 0; j < 4; j++) {
        hi[j] = __float2bfloat16(vv[j]);
        lo[j] = __float2bfloat16(vv[j] - __bfloat162float(hi[j]));
    }
    ((uint2*)g_whi)[i4] = *(uint2*)hi;
    ((uint2*)g_wlo)[i4] = *(uint2*)lo;
}

// =====================================================================
// Kernel A: mma.sync bf16-split xproj (unchanged from R14)
// =====================================================================
#define XA_HI 0
#define XA_LO 16384
#define XB_HI 32768
#define XB_LO 40960
#define XBUF  49152
#define XSMEM (2 * XBUF)

__global__ void __launch_bounds__(256, 2) xproj_tc_kernel(
    const float* __restrict__ br, const float* __restrict__ bz,
    const float* __restrict__ bg)
{
    extern __shared__ char smc[];
    const uint32_t smem_base = smem_u32(smc);
    const int tid = threadIdx.x;
    const int w = tid >> 5, lane = tid & 31;
    const int bn = blockIdx.x;
    const int bm = blockIdx.y;
    const int m0 = bm << 7;
    const int n0w = bn << 6;

    const int wm = w & 3;
    const int wn = w >> 2;

    auto issue = [&](int chunk, int buf) {
        const uint32_t base = smem_base + buf * XBUF;
        const __nv_bfloat16* sAh = g_xhi + (size_t)m0 * 512 + chunk * 64;
        const __nv_bfloat16* sAl = g_xlo + (size_t)m0 * 512 + chunk * 64;
        const __nv_bfloat16* sBh = g_whi + (size_t)n0w * 512 + chunk * 64;
        const __nv_bfloat16* sBl = g_wlo + (size_t)n0w * 512 + chunk * 64;
#pragma unroll
        for (int i = 0; i < 4; i++) {
            int id = tid + i * 256;
            int row = id >> 3, blk = id & 7;
            uint32_t off = row * 128 + ((blk ^ (row & 7)) << 4);
            cp16(base + XA_HI + off, sAh + (size_t)row * 512 + blk * 8);
            cp16(base + XA_LO + off, sAl + (size_t)row * 512 + blk * 8);
        }
#pragma unroll
        for (int i = 0; i < 2; i++) {
            int id = tid + i * 256;
            int row = id >> 3, blk = id & 7;
            uint32_t off = row * 128 + ((blk ^ (row & 7)) << 4);
            cp16(base + XB_HI + off, sBh + (size_t)row * 512 + blk * 8);
            cp16(base + XB_LO + off, sBl + (size_t)row * 512 + blk * 8);
        }
        CP_COMMIT();
    };

    float c[2][4][4];
#pragma unroll
    for (int mt = 0; mt < 2; mt++)
#pragma unroll
        for (int nt = 0; nt < 4; nt++)
#pragma unroll
            for (int q = 0; q < 4; q++) c[mt][nt][q] = 0.0f;

    issue(0, 0);

#pragma unroll 1
    for (int chunk = 0; chunk < 8; chunk++) {
        const int buf = chunk & 1;
        if (chunk < 7) { issue(chunk + 1, buf ^ 1); CP_WAIT1(); }
        else           { CP_WAIT0(); }
        __syncthreads();

        const uint32_t base = smem_base + buf * XBUF;
#pragma unroll
        for (int ks = 0; ks < 4; ks++) {
            uint32_t ahi[2][4], alo[2][4];
#pragma unroll
            for (int mt = 0; mt < 2; mt++) {
                int r  = wm * 32 + mt * 16 + (lane & 15);
                int cb = ks * 2 + (lane >> 4);
                uint32_t off = r * 128 + ((cb ^ (r & 7)) << 4);
                ldm4(ahi[mt], base + XA_HI + off);
                ldm4(alo[mt], base + XA_LO + off);
            }
            uint32_t bhi[4][2], blo[4][2];
#pragma unroll
            for (int p = 0; p < 2; p++) {
                int rn = wn * 32 + p * 16 + ((lane >> 4) << 3) + (lane & 7);
                int cb = ks * 2 + ((lane >> 3) & 1);
                uint32_t off = rn * 128 + ((cb ^ (rn & 7)) << 4);
                uint32_t th[4], tl[4];
                ldm4(th, base + XB_HI + off);
                ldm4(tl, base + XB_LO + off);
                bhi[p * 2 + 0][0] = th[0]; bhi[p * 2 + 0][1] = th[1];
                bhi[p * 2 + 1][0] = th[2]; bhi[p * 2 + 1][1] = th[3];
                blo[p * 2 + 0][0] = tl[0]; blo[p * 2 + 0][1] = tl[1];
                blo[p * 2 + 1][0] = tl[2]; blo[p * 2 + 1][1] = tl[3];
            }
#pragma unroll
            for (int mt = 0; mt < 2; mt++)
#pragma unroll
                for (int nt = 0; nt < 4; nt++) {
                    mma16816(c[mt][nt], ahi[mt], bhi[nt]);
                    mma16816(c[mt][nt], ahi[mt], blo[nt]);
                    mma16816(c[mt][nt], alo[mt], bhi[nt]);
                }
        }
        __syncthreads();
    }

    const int g = lane >> 2, tig = lane & 3;
#pragma unroll
    for (int mt = 0; mt < 2; mt++) {
        const int row0 = m0 + wm * 32 + mt * 16 + g;
#pragma unroll
        for (int nt = 0; nt < 4; nt++) {
            int ngb = n0w + wn * 32 + nt * 8;
            int gate = ngb >> 9;
            const float* bias = (gate == 0) ? br : (gate == 1) ? bz : bg;
            int nc = ngb + 2 * tig;
            float b0 = __ldg(&bias[nc & 511]);
            float b1 = __ldg(&bias[(nc & 511) + 1]);
            float2 v0 = {c[mt][nt][0] + b0, c[mt][nt][1] + b1};
            float2 v1 = {c[mt][nt][2] + b0, c[mt][nt][3] + b1};
            *(float2*)&g_Xbuf[(size_t)row0 * XCOLS + nc]       = v0;
            *(float2*)&g_Xbuf[(size_t)(row0 + 8) * XCOLS + nc] = v1;
        }
    }
}

// =====================================================================
// Recurrence helpers
// =====================================================================
__device__ __forceinline__ float dot4f(float4 a, float4 b) {
    return a.x * b.x + a.y * b.y + a.z * b.z + a.w * b.w;
}
__device__ __forceinline__ float fast_sigmoid(float v) {
    return 1.0f / (1.0f + __expf(-v));
}
__device__ __forceinline__ float fast_tanh(float v) {
    return 1.0f - 2.0f / (__expf(2.0f * v) + 1.0f);
}
__device__ __forceinline__ void reduce32(float* acc, int lane) {
#pragma unroll
    for (int off = 16; off >= 1; off >>= 1) {
        const int half = off;
        const bool up = (lane & off) != 0;
#pragma unroll
        for (int i = 0; i < 16; i++) {
            if (i < half) {
                float send = up ? acc[i] : acc[i + half];
                float got  = __shfl_xor_sync(0xffffffffu, send, off);
                acc[i] = (up ? acc[i + half] : acc[i]) + got;
            }
        }
    }
}
__device__ __forceinline__ void reduce16dup(float* acc, int lane) {
#pragma unroll
    for (int off = 16; off >= 2; off >>= 1) {
        const int half = off >> 1;
        const bool up = (lane & off) != 0;
#pragma unroll
        for (int i = 0; i < 8; i++) {
            if (i < half) {
                float send = up ? acc[i] : acc[i + half];
                float got  = __shfl_xor_sync(0xffffffffu, send, off);
                acc[i] = (up ? acc[i + half] : acc[i]) + got;
            }
        }
    }
    acc[0] += __shfl_xor_sync(0xffffffffu, acc[0], 1);
}

// =====================================================================
// Kernel B: persistent recurrence, 16-CTA CLUSTER per group.
// h / r*h live entirely in smem; each CTA writes its 32-col slice into
// all 16 peers' smem via DSMEM (st.shared::cluster.v4); 2 cluster
// barriers per step. No global h state, no L2 barriers, no staging.
// =====================================================================
__global__ void __launch_bounds__(RTHREADS, 1) __cluster_dims__(CPG, 1, 1)
gru_rec_kernel(
    float* __restrict__ out,
    const float* __restrict__ Wr,
    const float* __restrict__ Wz,
    const float* __restrict__ Wg,
    int write_final)
{
    extern __shared__ float sm[];
    float* wrz = sm;                    // [64][512]
    float* wg  = wrz + 64 * 512;        // [32][512]
    float* hsA = wg  + 32 * 512;        // [8][512]  h(t-1), all n, local batches
    float* hsB = hsA + 8 * 512;         // [8][512]  r*h, all n, local batches
    float* zs  = hsB + 8 * 512;         // [8][32]
    float* rst = zs  + 256;             // [8][32]   finalize staging (send src)

    const int cta = blockIdx.x;
    const int grp = cta >> 4;
    const int cid = cta & 15;           // == cluster rank
    const int n0 = cid * RPC;
    const int b0 = grp * BLOC;
    const int tid = threadIdx.x;
    const int w = tid >> 5, lane = tid & 31;

    const uint32_t hsA_u = smem_u32(hsA);
    const uint32_t hsB_u = smem_u32(hsB);

    // ---- load weights; zero hsA (fresh every launch -> deterministic) ----
    for (int idx = tid; idx < 64 * 128; idx += RTHREADS) {
        int row = idx >> 7, c4 = idx & 127;
        const float* W = (row < 32) ? Wr : Wz;
        int n = n0 + (row & 31);
        ((float4*)wrz)[idx] = *(const float4*)&W[(size_t)n * 1024 + 512 + c4 * 4];
    }
    for (int idx = tid; idx < 32 * 128; idx += RTHREADS) {
        int row = idx >> 7, c4 = idx & 127;
        ((float4*)wg)[idx] = *(const float4*)&Wg[(size_t)(n0 + row) * 1024 + 512 + c4 * 4];
    }
    {
        float4 z4 = {0.f, 0.f, 0.f, 0.f};
#pragma unroll
        for (int it = 0; it < 2; it++)
            ((float4*)hsA)[tid + it * RTHREADS] = z4;
    }
    __syncthreads();

    // phase1 mapping: warps 0..7 = r rows, 8..15 = z rows; 4 batches x 8 rows
    const int p1_bb  = (w & 1) * 4;
    const int p1_rb  = (w >> 1) * 8;                   // 0..56
    const int p1_bl  = p1_bb + (lane >> 3);
    const int p1_row = p1_rb + (lane & 7);             // 0..63
    const bool p1_isR = p1_row < 32;
    const int p1_nl  = p1_row & 31;
    const int p1_n   = n0 + p1_nl;
    const int p1_b   = b0 + p1_bl;
    const int p1_col = (p1_isR ? 0 : 512) + p1_n;
    // phase2 mapping: 4 batches x 4 rows per warp; output o2 = lane>>1
    const int p2_bb = (w & 1) * 4;
    const int p2_rb = (w >> 1) * 4;
    const int o2    = lane >> 1;
    const int p2_bl = p2_bb + (o2 >> 2);
    const int p2_nl = p2_rb + (o2 & 3);
    const int p2_b  = b0 + p2_bl;
    const int p2_n  = n0 + p2_nl;

    // DSMEM send mapping: 512 threads x 2 ranks; each covers one float4 of rst
    const int sf4   = tid & 63;                        // rst float4 index
    const int srank = (tid >> 6) << 1;                 // base rank (2 per thread)
    const uint32_t sdst_off =
        (uint32_t)(((sf4 >> 3) * 128 + cid * 8 + (sf4 & 7)) * 16);

    const float4* hsA4 = (const float4*)hsA;
    const float4* hsB4 = (const float4*)hsB;
    const float4* wrz4 = (const float4*)wrz;
    const float4* wg4  = (const float4*)wg;

    const float* xrow = g_Xbuf;
    for (int t = 0; t < T_STEPS; t++, xrow += (size_t)BATCH * XCOLS) {
        // prefetch this step's x pre-activations
        float x1v = __ldg(&xrow[(size_t)p1_b * XCOLS + p1_col]);
        float x2v = __ldg(&xrow[(size_t)p2_b * XCOLS + 1024 + p2_n]);

        // ================= phase 1: r and z (reads local hsA) ==============
        {
            float acc[32];
#pragma unroll
            for (int i = 0; i < 32; i++) acc[i] = 0.0f;
#pragma unroll
            for (int j = 0; j < 4; j++) {
                const int o = lane + j * 32;
                float4 hv[4];
#pragma unroll
                for (int bbx = 0; bbx < 4; bbx++)
                    hv[bbx] = hsA4[(p1_bb + bbx) * 128 + o];
#pragma unroll
                for (int rr = 0; rr < 8; rr++) {
                    float4 wv = wrz4[(p1_rb + rr) * 128 + o];
#pragma unroll
                    for (int bbx = 0; bbx < 4; bbx++)
                        acc[bbx * 8 + rr] += dot4f(hv[bbx], wv);
                }
            }
            reduce32(acc, lane);
            float sg = fast_sigmoid(x1v + acc[0]);
            if (p1_isR) {
                rst[p1_bl * 32 + p1_nl] = sg * hsA[p1_bl * 512 + p1_n];
            } else {
                zs[p1_bl * 32 + p1_nl] = sg;
            }
        }
        __syncthreads();
        // ---- broadcast r*h slice to all 16 peers' hsB (incl. self) ----
        {
            float4 v = ((const float4*)rst)[sf4];
            st_cluster_v4(mapa_u32(hsB_u + sdst_off, srank),     v);
            st_cluster_v4(mapa_u32(hsB_u + sdst_off, srank + 1), v);
        }
        CLUSTER_ARRIVE();
        CLUSTER_WAIT();

        // ================= phase 2: g and h update (reads local hsB) =======
        {
            float acc[16];
#pragma unroll
            for (int i = 0; i < 16; i++) acc[i] = 0.0f;
#pragma unroll
            for (int j = 0; j < 4; j++) {
                const int o = lane + j * 32;
                float4 hv[4];
#pragma unroll
                for (int bbx = 0; bbx < 4; bbx++)
                    hv[bbx] = hsB4[(p2_bb + bbx) * 128 + o];
#pragma unroll
                for (int rr = 0; rr < 4; rr++) {
                    float4 wv = wg4[(p2_rb + rr) * 128 + o];
#pragma unroll
                    for (int bbx = 0; bbx < 4; bbx++)
                        acc[bbx * 4 + rr] += dot4f(hv[bbx], wv);
                }
            }
            reduce16dup(acc, lane);
            if ((lane & 1) == 0) {
                float gv = fast_tanh(x2v + acc[0]);
                float zv = zs[p2_bl * 32 + p2_nl];
                float hp = hsA[p2_bl * 512 + p2_n];   // our slice: untouched yet
                float hn = zv * hp + (1.0f - zv) * gv;
                rst[p2_bl * 32 + p2_nl] = hn;
                out[((size_t)t * BATCH + p2_b) * 512 + p2_n] = hn;
                if (write_final && t == T_STEPS - 1)
                    out[(size_t)T_STEPS * BATCH * 512 + p2_b * 512 + p2_n] = hn;
            }
        }
        if (t < T_STEPS - 1) {
            __syncthreads();
            // ---- broadcast new h slice to all 16 peers' hsA ----
            {
                float4 v = ((const float4*)rst)[sf4];
                st_cluster_v4(mapa_u32(hsA_u + sdst_off, srank),     v);
                st_cluster_v4(mapa_u32(hsA_u + sdst_off, srank + 1), v);
            }
            CLUSTER_ARRIVE();
            CLUSTER_WAIT();
        }
    }
}

// =====================================================================
extern "C" void kernel_launch(void* const* d_in, const int* in_sizes, int n_in,
                              void* d_out, int out_size) {
    const float* x  = (const float*)d_in[0];
    const float* Wr = (const float*)d_in[1];
    const float* br = (const float*)d_in[2];
    const float* Wz = (const float*)d_in[3];
    const float* bz = (const float*)d_in[4];
    const float* Wg = (const float*)d_in[5];
    const float* bg = (const float*)d_in[6];
    float* out = (float*)d_out;

    // bf16 hi/lo splits
    split_x_kernel<<<(MROWS * D_IN) / (256 * 4), 256>>>(x);
    split_w_kernel<<<(XCOLS * D_IN) / (256 * 4), 256>>>(Wr, Wz, Wg);

    // tensor-core (mma.sync) input projection
    cudaFuncSetAttribute(xproj_tc_kernel,
                         cudaFuncAttributeMaxDynamicSharedMemorySize, XSMEM);
    dim3 gtc(24, 1024);
    xproj_tc_kernel<<<gtc, 256, XSMEM>>>(br, bz, bg);

    long long need = (long long)T_STEPS * BATCH * D_HID + (long long)BATCH * D_HID;
    int write_final = ((long long)out_size >= need) ? 1 : 0;

    // cluster-16 persistent recurrence
    // smem: wrz 131072 + wg 65536 + hsA 16384 + hsB 16384 + zs 1024 + rst 1024
    const int smem_bytes = (64 * 512 + 32 * 512 + 8 * 512 + 8 * 512 + 256 + 256) * 4;
    cudaFuncSetAttribute(gru_rec_kernel,
                         cudaFuncAttributeNonPortableClusterSizeAllowed, 1);
    cudaFuncSetAttribute(gru_rec_kernel,
                         cudaFuncAttributeMaxDynamicSharedMemorySize, smem_bytes);
    gru_rec_kernel<<<NCTAS, RTHREADS, smem_bytes>>>(out, Wr, Wz, Wg, write_final);
}

// round 17
// speedup vs baseline: 1.4940x; 1.4940x over previous
#include <cuda_runtime.h>
#include <cuda_bf16.h>
#include <math.h>
#include <stdint.h>
#include <stddef.h>

// ---------------- problem constants ----------------
#define T_STEPS 2048
#define BATCH   64
#define D_IN    512
#define D_HID   512
#define MROWS   (T_STEPS * BATCH)        // 131072
#define XCOLS   1536                     // r | z | g pre-activations from x

// ---------------- recurrent kernel topology ----------------
#define NGROUPS 8
#define CPG     16
#define NCTAS   (NGROUPS * CPG)          // 128
#define BLOC    (BATCH / NGROUPS)        // 8
#define RPC     (D_HID / CPG)            // 32
#define RTHREADS 512

// ---------------- device scratch (static; no allocation APIs) ----------------
__device__ float g_Xbuf[(size_t)MROWS * XCOLS];
__device__ float g_h[BATCH * D_HID];
__device__ float g_rh[BATCH * D_HID];
__device__ unsigned g_cnt1[NGROUPS];
__device__ unsigned g_gen1[NGROUPS];
__device__ unsigned g_cnt2[NGROUPS];
__device__ unsigned g_gen2[NGROUPS];

// bf16 hi/lo split operands for the tensor-core xproj
__device__ __nv_bfloat16 g_xhi[(size_t)MROWS * D_IN];
__device__ __nv_bfloat16 g_xlo[(size_t)MROWS * D_IN];
__device__ __nv_bfloat16 g_whi[XCOLS * D_IN];
__device__ __nv_bfloat16 g_wlo[XCOLS * D_IN];

// ---------------- acquire/release sync primitives ----------------
__device__ __forceinline__ unsigned ld_acq(const unsigned* p) {
    unsigned v;
    asm volatile("ld.acquire.gpu.u32 %0, [%1];" : "=r"(v) : "l"(p) : "memory");
    return v;
}
__device__ __forceinline__ unsigned atom_add_rel(unsigned* p, unsigned v) {
    unsigned old;
    asm volatile("atom.add.release.gpu.u32 %0, [%1], %2;"
                 : "=r"(old) : "l"(p), "r"(v) : "memory");
    return old;
}
__device__ __forceinline__ void st_rel_u32(unsigned* p, unsigned v) {
    asm volatile("st.release.gpu.u32 [%0], %1;" :: "l"(p), "r"(v) : "memory");
}
__device__ __forceinline__ void st_rlx_u32(unsigned* p, unsigned v) {
    asm volatile("st.relaxed.gpu.u32 [%0], %1;" :: "l"(p), "r"(v) : "memory");
}
__device__ __forceinline__ void stg_strong(float* p, float v) {
    asm volatile("st.relaxed.gpu.f32 [%0], %1;" :: "l"(p), "f"(v) : "memory");
}

// ---------------- mma.sync / ldmatrix / cp.async helpers -------------------
__device__ __forceinline__ uint32_t smem_u32(const void* p) {
    uint32_t a;
    asm("{ .reg .u64 t; cvta.to.shared.u64 t, %1; cvt.u32.u64 %0, t; }"
        : "=r"(a) : "l"(p));
    return a;
}
__device__ __forceinline__ void ldm4(uint32_t* r, uint32_t addr) {
    asm volatile("ldmatrix.sync.aligned.m8n8.x4.shared.b16 {%0,%1,%2,%3}, [%4];"
                 : "=r"(r[0]), "=r"(r[1]), "=r"(r[2]), "=r"(r[3]) : "r"(addr));
}
__device__ __forceinline__ void ldm2(uint32_t* r, uint32_t addr) {
    asm volatile("ldmatrix.sync.aligned.m8n8.x2.shared.b16 {%0,%1}, [%2];"
                 : "=r"(r[0]), "=r"(r[1]) : "r"(addr));
}
__device__ __forceinline__ void mma16816(float* c, const uint32_t* a,
                                         const uint32_t* b) {
    asm volatile(
        "mma.sync.aligned.m16n8k16.row.col.f32.bf16.bf16.f32 "
        "{%0,%1,%2,%3}, {%4,%5,%6,%7}, {%8,%9}, {%0,%1,%2,%3};"
        : "+f"(c[0]), "+f"(c[1]), "+f"(c[2]), "+f"(c[3])
        : "r"(a[0]), "r"(a[1]), "r"(a[2]), "r"(a[3]), "r"(b[0]), "r"(b[1]));
}
__device__ __forceinline__ void cp16(uint32_t dst, const void* src) {
    asm volatile("cp.async.cg.shared.global [%0], [%1], 16;"
                 :: "r"(dst), "l"(__cvta_generic_to_global(src)) : "memory");
}
#define CP_COMMIT() asm volatile("cp.async.commit_group;" ::: "memory")
#define CP_WAIT1()  asm volatile("cp.async.wait_group 1;" ::: "memory")
#define CP_WAIT0()  asm volatile("cp.async.wait_group 0;" ::: "memory")

// split one fp32 into bf16 hi (truncate) + bf16 lo (rounded remainder)
__device__ __forceinline__ void split1(float v, unsigned short& hb,
                                       unsigned short& lb) {
    uint32_t u = __float_as_uint(v);
    hb = (unsigned short)(u >> 16);
    float hif = __uint_as_float(u & 0xffff0000u);
    lb = __bfloat16_as_ushort(__float2bfloat16(v - hif));
}

// =====================================================================
// split kernels: fp32 -> bf16 hi + bf16 lo   (unchanged from R14)
// =====================================================================
__global__ void __launch_bounds__(256) split_x_kernel(const float* __restrict__ x) {
    size_t i4 = (size_t)blockIdx.x * 256 + threadIdx.x;
    float4 v = ((const float4*)x)[i4];
    float vv[4] = {v.x, v.y, v.z, v.w};
    __nv_bfloat16 hi[4], lo[4];
#pragma unroll
    for (int j = 0; j < 4; j++) {
        hi[j] = __float2bfloat16(vv[j]);
        lo[j] = __float2bfloat16(vv[j] - __bfloat162float(hi[j]));
    }
    ((uint2*)g_xhi)[i4] = *(uint2*)hi;
    ((uint2*)g_xlo)[i4] = *(uint2*)lo;
}

__global__ void __launch_bounds__(256) split_w_kernel(
    const float* __restrict__ Wr, const float* __restrict__ Wz,
    const float* __restrict__ Wg)
{
    size_t i4 = (size_t)blockIdx.x * 256 + threadIdx.x;
    size_t e = i4 * 4;
    int n = (int)(e >> 9);
    int k = (int)(e & 511);
    int gate = n >> 9;
    int nr = n & 511;
    const float* W = (gate == 0) ? Wr : (gate == 1) ? Wz : Wg;
    float4 v = *(const float4*)&W[(size_t)nr * 1024 + k];
    float vv[4] = {v.x, v.y, v.z, v.w};
    __nv_bfloat16 hi[4], lo[4];
#pragma unroll
    for (int j = 0; j < 4; j++) {
        hi[j] = __float2bfloat16(vv[j]);
        lo[j] = __float2bfloat16(vv[j] - __bfloat162float(hi[j]));
    }
    ((uint2*)g_whi)[i4] = *(uint2*)hi;
    ((uint2*)g_wlo)[i4] = *(uint2*)lo;
}

// =====================================================================
// Kernel A: mma.sync bf16-split xproj (unchanged from R14)
// =====================================================================
#define XA_HI 0
#define XA_LO 16384
#define XB_HI 32768
#define XB_LO 40960
#define XBUF  49152
#define XSMEM (2 * XBUF)

__global__ void __launch_bounds__(256, 2) xproj_tc_kernel(
    const float* __restrict__ br, const float* __restrict__ bz,
    const float* __restrict__ bg)
{
    extern __shared__ char smc[];
    const uint32_t smem_base = smem_u32(smc);
    const int tid = threadIdx.x;
    const int w = tid >> 5, lane = tid & 31;
    const int bn = blockIdx.x;
    const int bm = blockIdx.y;
    const int m0 = bm << 7;
    const int n0w = bn << 6;

    const int wm = w & 3;
    const int wn = w >> 2;

    auto issue = [&](int chunk, int buf) {
        const uint32_t base = smem_base + buf * XBUF;
        const __nv_bfloat16* sAh = g_xhi + (size_t)m0 * 512 + chunk * 64;
        const __nv_bfloat16* sAl = g_xlo + (size_t)m0 * 512 + chunk * 64;
        const __nv_bfloat16* sBh = g_whi + (size_t)n0w * 512 + chunk * 64;
        const __nv_bfloat16* sBl = g_wlo + (size_t)n0w * 512 + chunk * 64;
#pragma unroll
        for (int i = 0; i < 4; i++) {
            int id = tid + i * 256;
            int row = id >> 3, blk = id & 7;
            uint32_t off = row * 128 + ((blk ^ (row & 7)) << 4);
            cp16(base + XA_HI + off, sAh + (size_t)row * 512 + blk * 8);
            cp16(base + XA_LO + off, sAl + (size_t)row * 512 + blk * 8);
        }
#pragma unroll
        for (int i = 0; i < 2; i++) {
            int id = tid + i * 256;
            int row = id >> 3, blk = id & 7;
            uint32_t off = row * 128 + ((blk ^ (row & 7)) << 4);
            cp16(base + XB_HI + off, sBh + (size_t)row * 512 + blk * 8);
            cp16(base + XB_LO + off, sBl + (size_t)row * 512 + blk * 8);
        }
        CP_COMMIT();
    };

    float c[2][4][4];
#pragma unroll
    for (int mt = 0; mt < 2; mt++)
#pragma unroll
        for (int nt = 0; nt < 4; nt++)
#pragma unroll
            for (int q = 0; q < 4; q++) c[mt][nt][q] = 0.0f;

    issue(0, 0);

#pragma unroll 1
    for (int chunk = 0; chunk < 8; chunk++) {
        const int buf = chunk & 1;
        if (chunk < 7) { issue(chunk + 1, buf ^ 1); CP_WAIT1(); }
        else           { CP_WAIT0(); }
        __syncthreads();

        const uint32_t base = smem_base + buf * XBUF;
#pragma unroll
        for (int ks = 0; ks < 4; ks++) {
            uint32_t ahi[2][4], alo[2][4];
#pragma unroll
            for (int mt = 0; mt < 2; mt++) {
                int r  = wm * 32 + mt * 16 + (lane & 15);
                int cb = ks * 2 + (lane >> 4);
                uint32_t off = r * 128 + ((cb ^ (r & 7)) << 4);
                ldm4(ahi[mt], base + XA_HI + off);
                ldm4(alo[mt], base + XA_LO + off);
            }
            uint32_t bhi[4][2], blo[4][2];
#pragma unroll
            for (int p = 0; p < 2; p++) {
                int rn = wn * 32 + p * 16 + ((lane >> 4) << 3) + (lane & 7);
                int cb = ks * 2 + ((lane >> 3) & 1);
                uint32_t off = rn * 128 + ((cb ^ (rn & 7)) << 4);
                uint32_t th[4], tl[4];
                ldm4(th, base + XB_HI + off);
                ldm4(tl, base + XB_LO + off);
                bhi[p * 2 + 0][0] = th[0]; bhi[p * 2 + 0][1] = th[1];
                bhi[p * 2 + 1][0] = th[2]; bhi[p * 2 + 1][1] = th[3];
                blo[p * 2 + 0][0] = tl[0]; blo[p * 2 + 0][1] = tl[1];
                blo[p * 2 + 1][0] = tl[2]; blo[p * 2 + 1][1] = tl[3];
            }
#pragma unroll
            for (int mt = 0; mt < 2; mt++)
#pragma unroll
                for (int nt = 0; nt < 4; nt++) {
                    mma16816(c[mt][nt], ahi[mt], bhi[nt]);
                    mma16816(c[mt][nt], ahi[mt], blo[nt]);
                    mma16816(c[mt][nt], alo[mt], bhi[nt]);
                }
        }
        __syncthreads();
    }

    const int g = lane >> 2, tig = lane & 3;
#pragma unroll
    for (int mt = 0; mt < 2; mt++) {
        const int row0 = m0 + wm * 32 + mt * 16 + g;
#pragma unroll
        for (int nt = 0; nt < 4; nt++) {
            int ngb = n0w + wn * 32 + nt * 8;
            int gate = ngb >> 9;
            const float* bias = (gate == 0) ? br : (gate == 1) ? bz : bg;
            int nc = ngb + 2 * tig;
            float b0 = __ldg(&bias[nc & 511]);
            float b1 = __ldg(&bias[(nc & 511) + 1]);
            float2 v0 = {c[mt][nt][0] + b0, c[mt][nt][1] + b1};
            float2 v1 = {c[mt][nt][2] + b0, c[mt][nt][3] + b1};
            *(float2*)&g_Xbuf[(size_t)row0 * XCOLS + nc]       = v0;
            *(float2*)&g_Xbuf[(size_t)(row0 + 8) * XCOLS + nc] = v1;
        }
    }
}

// =====================================================================
// Kernel B: persistent recurrence with TENSOR-CORE phases.
//   phase1: C1[64,8] = Wrz_h[64,512] . h^T       (bf16 split, 3 products)
//   phase2: C2[32,8] = Wg_h[32,512] . (r*h)^T
// Weights bf16 hi/lo in smem (XOR-granule swizzle); h / r*h staged from
// L2 each phase and converted; own-slice h kept exact fp32 (state
// lineage stays fp32). Sync fabric = R12 acq/rel barriers.
// =====================================================================
#define RS_WRZH 0                       // [64][512] bf16
#define RS_WRZL (RS_WRZH + 65536)
#define RS_WGH  (RS_WRZL + 65536)       // [32][512] bf16
#define RS_WGL  (RS_WGH + 32768)
#define RS_HBH  (RS_WGL + 32768)        // [8][512] bf16  (h / r*h hi)
#define RS_HBL  (RS_HBH + 8192)
#define RS_PART (RS_HBL + 8192)         // [2048] fp32 partials
#define RS_ZS   (RS_PART + 8192)        // [8][32] fp32 z
#define RS_HFO  (RS_ZS + 1024)          // [8][32] fp32 own-slice h (exact)
#define RSMEM   (RS_HFO + 1024)         // 223232 bytes

__global__ void __launch_bounds__(RTHREADS, 1) gru_rec_kernel(
    float* __restrict__ out,
    const float* __restrict__ Wr,
    const float* __restrict__ Wz,
    const float* __restrict__ Wg,
    int write_final)
{
    extern __shared__ char smc[];
    unsigned short* wrzh = (unsigned short*)(smc + RS_WRZH);
    unsigned short* wrzl = (unsigned short*)(smc + RS_WRZL);
    unsigned short* wgh  = (unsigned short*)(smc + RS_WGH);
    unsigned short* wgl  = (unsigned short*)(smc + RS_WGL);
    float* part  = (float*)(smc + RS_PART);
    float* zs    = (float*)(smc + RS_ZS);
    float* hfo   = (float*)(smc + RS_HFO);

    const uint32_t u_wrzh = smem_u32(smc + RS_WRZH);
    const uint32_t u_wrzl = smem_u32(smc + RS_WRZL);
    const uint32_t u_wgh  = smem_u32(smc + RS_WGH);
    const uint32_t u_wgl  = smem_u32(smc + RS_WGL);
    const uint32_t u_hbh  = smem_u32(smc + RS_HBH);
    const uint32_t u_hbl  = smem_u32(smc + RS_HBL);

    const int cta = blockIdx.x;
    const int grp = cta >> 4;
    const int cid = cta & 15;
    const int n0 = cid * RPC;           // owned hidden rows [n0, n0+32)
    const int b0 = grp * BLOC;          // owned batches    [b0, b0+8)
    const int tid = threadIdx.x;
    const int w = tid >> 5, lane = tid & 31;

    // ---- one-time: weights -> smem bf16 hi/lo, XOR-granule swizzle ----
    for (int task = tid; task < 64 * 64; task += RTHREADS) {   // wrz
        int row = task >> 6, gg = task & 63;
        const float* W = (row < 32) ? Wr : Wz;
        int n = n0 + (row & 31);
        const float* src = &W[(size_t)n * 1024 + 512 + gg * 8];
        float4 v0 = *(const float4*)src, v1 = *(const float4*)(src + 4);
        float vv[8] = {v0.x, v0.y, v0.z, v0.w, v1.x, v1.y, v1.z, v1.w};
        unsigned short hb[8], lb[8];
#pragma unroll
        for (int j = 0; j < 8; j++) split1(vv[j], hb[j], lb[j]);
        uint32_t off = row * 1024 + ((gg ^ (row & 7)) << 4);
        *(uint4*)((char*)wrzh + off) = *(uint4*)hb;
        *(uint4*)((char*)wrzl + off) = *(uint4*)lb;
    }
    for (int task = tid; task < 32 * 64; task += RTHREADS) {   // wg
        int row = task >> 6, gg = task & 63;
        const float* src = &Wg[(size_t)(n0 + row) * 1024 + 512 + gg * 8];
        float4 v0 = *(const float4*)src, v1 = *(const float4*)(src + 4);
        float vv[8] = {v0.x, v0.y, v0.z, v0.w, v1.x, v1.y, v1.z, v1.w};
        unsigned short hb[8], lb[8];
#pragma unroll
        for (int j = 0; j < 8; j++) split1(vv[j], hb[j], lb[j]);
        uint32_t off = row * 1024 + ((gg ^ (row & 7)) << 4);
        *(uint4*)((char*)wgh + off) = *(uint4*)hb;
        *(uint4*)((char*)wgl + off) = *(uint4*)lb;
    }
    __syncthreads();

    // staging task mapping: thread tid -> (batch st_bl, granule st_g)
    const int st_bl = tid >> 6;                 // 0..7
    const int st_g  = tid & 63;                 // 0..63
    const uint32_t st_off = st_bl * 1024 + ((st_g ^ (st_bl & 7)) << 4);
    const bool st_own = (st_g >= (n0 >> 3)) && (st_g < (n0 >> 3) + 4);
    const int st_ko = st_g * 8 - n0;

    // phase1 finalize mapping: slot s = tid (0..511)
    const int f1_mt   = tid >> 7;
    const int f1_lane = (tid & 127) >> 2;
    const int f1_ci   = tid & 3;
    const int f1_m    = f1_mt * 16 + (f1_lane >> 2) + ((f1_ci >= 2) ? 8 : 0);
    const int f1_nb   = 2 * (f1_lane & 3) + (f1_ci & 1);
    const int f1_b    = b0 + f1_nb;
    const int f1_col  = (f1_m < 32) ? (n0 + f1_m) : (512 + n0 + (f1_m - 32));
    // phase2 finalize mapping (tid < 256)
    const int f2_mt   = (tid >> 7) & 1;
    const int f2_m    = f2_mt * 16 + (f1_lane >> 2) + ((f1_ci >= 2) ? 8 : 0);
    const int f2_nb   = f1_nb;
    const int f2_b    = b0 + f2_nb;

    // warp mappings
    const int p1_mt = w & 3, p1_kg = w >> 2;
    const int p1_r  = p1_mt * 16 + (lane & 15);
    const int p2_mt = w & 1, p2_kg = w >> 1;
    const int p2_r  = p2_mt * 16 + (lane & 15);
    const int bB_row = lane & 7;
    const int bB_sel = (lane >> 3) & 1;
    const uint32_t bB_base = bB_row * 1024;
    const int bB_swz = bB_row & 7;

    const float* xrow = g_Xbuf;
    for (int t = 0; t < T_STEPS; t++, xrow += (size_t)BATCH * XCOLS) {
        const unsigned my1 = ld_acq(&g_gen1[grp]);
        const unsigned my2 = ld_acq(&g_gen2[grp]);

        float x1v = __ldg(&xrow[(size_t)f1_b * XCOLS + f1_col]);
        float x2v = 0.0f;
        if (tid < 256)
            x2v = __ldg(&xrow[(size_t)f2_b * XCOLS + 1024 + n0 + f2_m]);

        // ---- stage h -> hbh/hbl (+ own slice fp32) ----
        if (t == 0) {
            uint4 z4 = {0u, 0u, 0u, 0u};
            *(uint4*)(smc + RS_HBH + st_off) = z4;
            *(uint4*)(smc + RS_HBL + st_off) = z4;
            if (st_own) {
#pragma unroll
                for (int j = 0; j < 8; j++) hfo[st_bl * 32 + st_ko + j] = 0.0f;
            }
        } else {
            const float* src = &g_h[(b0 + st_bl) * 512 + st_g * 8];
            float4 v0 = __ldcg((const float4*)src);
            float4 v1 = __ldcg((const float4*)(src + 4));
            float vv[8] = {v0.x, v0.y, v0.z, v0.w, v1.x, v1.y, v1.z, v1.w};
            unsigned short hb[8], lb[8];
#pragma unroll
            for (int j = 0; j < 8; j++) split1(vv[j], hb[j], lb[j]);
            *(uint4*)(smc + RS_HBH + st_off) = *(uint4*)hb;
            *(uint4*)(smc + RS_HBL + st_off) = *(uint4*)lb;
            if (st_own) {
#pragma unroll
                for (int j = 0; j < 8; j++) hfo[st_bl * 32 + st_ko + j] = vv[j];
            }
        }
        __syncthreads();

        // ================= phase 1 mma: Wrz . h^T =================
        {
            float c[4] = {0.f, 0.f, 0.f, 0.f};
#pragma unroll
            for (int j = 0; j < 8; j++) {
                int kb = p1_kg * 8 + j;
                int cbA = kb * 2 + (lane >> 4);
                uint32_t offA = p1_r * 1024 + ((cbA ^ (p1_r & 7)) << 4);
                uint32_t ah[4], al[4];
                ldm4(ah, u_wrzh + offA);
                ldm4(al, u_wrzl + offA);
                int cbB = kb * 2 + bB_sel;
                uint32_t offB = bB_base + ((cbB ^ bB_swz) << 4);
                uint32_t bh[2], blv[2];
                ldm2(bh,  u_hbh + offB);
                ldm2(blv, u_hbl + offB);
                mma16816(c, ah, bh);
                mma16816(c, ah, blv);
                mma16816(c, al, bh);
            }
            *(float4*)&part[w * 128 + lane * 4] = *(float4*)c;
        }
        __syncthreads();
        // ---- reduce over 4 k-groups + finalize r/z ----
        {
            int s = tid;
            float v = part[s] + part[512 + s] + part[1024 + s] + part[1536 + s];
            float sg = 1.0f / (1.0f + __expf(-(x1v + v)));
            int m31 = f1_m & 31;
            float hv = hfo[f1_nb * 32 + m31];
            if (f1_m < 32) {
                stg_strong(&g_rh[f1_b * 512 + n0 + m31], sg * hv);
            } else {
                zs[f1_nb * 32 + m31] = sg;
            }
        }
        // ---- barrier 1 ----
        __syncthreads();
        if (tid == 0) {
            unsigned old = atom_add_rel(&g_cnt1[grp], 1u);
            if (old == CPG - 1u) {
                st_rlx_u32(&g_cnt1[grp], 0u);
                st_rel_u32(&g_gen1[grp], my1 + 1u);
            }
            while (ld_acq(&g_gen1[grp]) == my1) { }
        }
        __syncthreads();

        // ---- stage r*h -> hbh/hbl (overwrite) ----
        {
            const float* src = &g_rh[(b0 + st_bl) * 512 + st_g * 8];
            float4 v0 = __ldcg((const float4*)src);
            float4 v1 = __ldcg((const float4*)(src + 4));
            float vv[8] = {v0.x, v0.y, v0.z, v0.w, v1.x, v1.y, v1.z, v1.w};
            unsigned short hb[8], lb[8];
#pragma unroll
            for (int j = 0; j < 8; j++) split1(vv[j], hb[j], lb[j]);
            *(uint4*)(smc + RS_HBH + st_off) = *(uint4*)hb;
            *(uint4*)(smc + RS_HBL + st_off) = *(uint4*)lb;
        }
        __syncthreads();

        // ================= phase 2 mma: Wg . (r*h)^T =================
        {
            float c[4] = {0.f, 0.f, 0.f, 0.f};
#pragma unroll
            for (int j = 0; j < 4; j++) {
                int kb = p2_kg * 4 + j;
                int cbA = kb * 2 + (lane >> 4);
                uint32_t offA = p2_r * 1024 + ((cbA ^ (p2_r & 7)) << 4);
                uint32_t ah[4], al[4];
                ldm4(ah, u_wgh + offA);
                ldm4(al, u_wgl + offA);
                int cbB = kb * 2 + bB_sel;
                uint32_t offB = bB_base + ((cbB ^ bB_swz) << 4);
                uint32_t bh[2], blv[2];
                ldm2(bh,  u_hbh + offB);
                ldm2(blv, u_hbl + offB);
                mma16816(c, ah, bh);
                mma16816(c, ah, blv);
                mma16816(c, al, bh);
            }
            *(float4*)&part[w * 128 + lane * 4] = *(float4*)c;
        }
        __syncthreads();
        // ---- reduce over 8 k-groups + finalize h ----
        if (tid < 256) {
            float v = 0.0f;
#pragma unroll
            for (int kg = 0; kg < 8; kg++) v += part[kg * 256 + tid];
            float gv = 1.0f - 2.0f / (__expf(2.0f * (x2v + v)) + 1.0f);
            float zv = zs[f2_nb * 32 + f2_m];
            float hp = hfo[f2_nb * 32 + f2_m];
            float hn = zv * hp + (1.0f - zv) * gv;
            stg_strong(&g_h[f2_b * 512 + n0 + f2_m], hn);
            out[((size_t)t * BATCH + f2_b) * 512 + n0 + f2_m] = hn;
            if (write_final && t == T_STEPS - 1)
                out[(size_t)T_STEPS * BATCH * 512 + f2_b * 512 + n0 + f2_m] = hn;
        }
        // ---- barrier 2 ----
        __syncthreads();
        if (tid == 0) {
            unsigned old = atom_add_rel(&g_cnt2[grp], 1u);
            if (old == CPG - 1u) {
                st_rlx_u32(&g_cnt2[grp], 0u);
                st_rel_u32(&g_gen2[grp], my2 + 1u);
            }
            if (t < T_STEPS - 1) {
                while (ld_acq(&g_gen2[grp]) == my2) { }
            }
        }
        if (t < T_STEPS - 1) __syncthreads();
    }
}

// =====================================================================
extern "C" void kernel_launch(void* const* d_in, const int* in_sizes, int n_in,
                              void* d_out, int out_size) {
    const float* x  = (const float*)d_in[0];
    const float* Wr = (const float*)d_in[1];
    const float* br = (const float*)d_in[2];
    const float* Wz = (const float*)d_in[3];
    const float* bz = (const float*)d_in[4];
    const float* Wg = (const float*)d_in[5];
    const float* bg = (const float*)d_in[6];
    float* out = (float*)d_out;

    split_x_kernel<<<(MROWS * D_IN) / (256 * 4), 256>>>(x);
    split_w_kernel<<<(XCOLS * D_IN) / (256 * 4), 256>>>(Wr, Wz, Wg);

    cudaFuncSetAttribute(xproj_tc_kernel,
                         cudaFuncAttributeMaxDynamicSharedMemorySize, XSMEM);
    dim3 gtc(24, 1024);
    xproj_tc_kernel<<<gtc, 256, XSMEM>>>(br, bz, bg);

    long long need = (long long)T_STEPS * BATCH * D_HID + (long long)BATCH * D_HID;
    int write_final = ((long long)out_size >= need) ? 1 : 0;

    cudaFuncSetAttribute(gru_rec_kernel,
                         cudaFuncAttributeMaxDynamicSharedMemorySize, RSMEM);
    gru_rec_kernel<<<NCTAS, RTHREADS, RSMEM>>>(out, Wr, Wz, Wg, write_final);
}